// round 9
// baseline (speedup 1.0000x reference)
#include <cuda_runtime.h>
#include <cuda_fp16.h>
#include <cstdint>

// ============================================================================
// dims
// ============================================================================
#define B_DIM 32
#define F_DIM 1024
#define L_DIM 1000
#define N_DIM 2048
#define LPAD  1024

// GEMM tiling (per batch: M=N_DIM rows n, N=L cols l, K=F)
#define TM 128
#define TN 128
#define KC 32                    // K (f) per stage
#define STAGES 3
#define KITERS (F_DIM / KC)      // 32

// SMEM layout per stage: A fp16 (128 rows x 80B) + Braw fp32 (32 rows x 512B)
#define RSTRIDE_A 80
#define A_STAGE_BYTES (TM * RSTRIDE_A)                     // 10240
#define BRAW_ROW_BYTES 512
#define BRAW_STAGE_BYTES (KC * BRAW_ROW_BYTES)             // 16384
#define STAGE_BYTES (A_STAGE_BYTES + BRAW_STAGE_BYTES)     // 26624
// Bh: converted fp16 B tile, [f 32][l 128], 272B row stride (68w = 4 mod 32)
#define BH_STRIDE 272
#define BH_OFF (STAGES * STAGE_BYTES)                      // 79872
#define BH_BYTES (KC * BH_STRIDE)                          // 8704
#define SMEM_BYTES (BH_OFF + BH_BYTES)                     // 88576

// ============================================================================
// device scratch (static globals: allocation-guard safe)
// ============================================================================
__device__ __align__(1024) __half g_A[(size_t)N_DIM * F_DIM];   // 4 MB

// ============================================================================
// helpers
// ============================================================================
__device__ __forceinline__ uint32_t smem_u32(const void* p) {
    uint32_t a;
    asm("{ .reg .u64 t; cvta.to.shared.u64 t, %1; cvt.u32.u64 %0, t; }"
        : "=r"(a) : "l"(p));
    return a;
}

#define CP_ASYNC16(dst, src) \
    asm volatile("cp.async.cg.shared.global [%0], [%1], 16;" \
                 :: "r"(dst), "l"(src) : "memory")
// src-size form: copies sz bytes (0 or 16), zero-fills the rest of 16
#define CP_ASYNC16_SZ(dst, src, sz) \
    asm volatile("cp.async.cg.shared.global [%0], [%1], 16, %2;" \
                 :: "r"(dst), "l"(src), "r"(sz) : "memory")
#define CP_COMMIT() asm volatile("cp.async.commit_group;" ::: "memory")
#define CP_WAIT(n)  asm volatile("cp.async.wait_group %0;" :: "n"(n) : "memory")

#define LDSM_X4(r0, r1, r2, r3, addr) \
    asm volatile("ldmatrix.sync.aligned.m8n8.x4.shared.b16 {%0,%1,%2,%3}, [%4];" \
                 : "=r"(r0), "=r"(r1), "=r"(r2), "=r"(r3) : "r"(addr))
#define LDSM_X4_T(r0, r1, r2, r3, addr) \
    asm volatile("ldmatrix.sync.aligned.m8n8.x4.trans.shared.b16 {%0,%1,%2,%3}, [%4];" \
                 : "=r"(r0), "=r"(r1), "=r"(r2), "=r"(r3) : "r"(addr))

__device__ __forceinline__ void mma_f16(float d[4],
                                        uint32_t a0, uint32_t a1,
                                        uint32_t a2, uint32_t a3,
                                        uint32_t b0, uint32_t b1) {
    asm volatile(
        "mma.sync.aligned.m16n8k16.row.col.f32.f16.f16.f32 "
        "{%0, %1, %2, %3}, {%4, %5, %6, %7}, {%8, %9}, {%0, %1, %2, %3};"
        : "+f"(d[0]), "+f"(d[1]), "+f"(d[2]), "+f"(d[3])
        : "r"(a0), "r"(a1), "r"(a2), "r"(a3), "r"(b0), "r"(b1));
}

// ============================================================================
// prep: A[n][f] = fp16(C[f][n] * W[n])
// ============================================================================
__global__ void prep_a_kernel(const float* __restrict__ C,
                              const float* __restrict__ W) {
    __shared__ float tile[32][33];
    const int n0 = blockIdx.x * 32;
    const int f0 = blockIdx.y * 32;
    const int tx = threadIdx.x, ty = threadIdx.y;
    const float w = W[n0 + tx];
#pragma unroll
    for (int i = 0; i < 32; i += 8)
        tile[ty + i][tx] = C[(size_t)(f0 + ty + i) * N_DIM + n0 + tx] * w;
    __syncthreads();
    if (tx < 16) {
#pragma unroll
        for (int i = 0; i < 32; i += 8) {
            const int n = n0 + ty + i;
            __half2 v = __floats2half2_rn(tile[2 * tx][ty + i],
                                          tile[2 * tx + 1][ty + i]);
            *reinterpret_cast<__half2*>(g_A + (size_t)n * F_DIM + f0 + 2 * tx) = v;
        }
    }
}

// ============================================================================
// fused GEMM: out[b, n0:+128, l0:+128] = A x X^T   (X fp32 converted in-flight)
//   128 threads = 4 warps: 2(m) x 2(n), warp tile 64 x 64
//   A: fp16 cp.async + ldmatrix       (as R8)
//   B: fp32 X tiles cp.async -> per-warp fp16 convert -> ldmatrix.trans
// ============================================================================
__global__ void __launch_bounds__(128, 2)
gemm_kernel(float* __restrict__ out, const float* __restrict__ X) {
    extern __shared__ __align__(128) char smem[];
    const uint32_t sbase = smem_u32(smem);
    const uint32_t sbh = sbase + BH_OFF;

    const int tid = threadIdx.x;
    const int wid = tid >> 5;
    const int lid = tid & 31;
    const int g = lid >> 2;
    const int t = lid & 3;

    const int wm = wid & 1;          // 0..1 -> 64 m-rows each
    const int wn = wid >> 1;         // 0..1 -> 64 n(l)-cols each

    const int n0 = blockIdx.x * TM;
    const int l0 = blockIdx.y * TN;
    const int b  = blockIdx.z;

    const __half* Abase = g_A + (size_t)n0 * F_DIM;
    const float*  Xb    = X + (size_t)b * F_DIM * L_DIM;
    const size_t  xtotal = (size_t)B_DIM * F_DIM * L_DIM;  // element count

    float d[4][8][4];
#pragma unroll
    for (int mi = 0; mi < 4; mi++)
#pragma unroll
        for (int ni = 0; ni < 8; ni++)
#pragma unroll
            for (int r = 0; r < 4; r++) d[mi][ni][r] = 0.0f;

    // A cp.async mapping: 128 rows x 4 chunks of 16B (as R8)
    const int a_row = tid >> 2;      // 0..31 (+32 per i)
    const int a_cb  = tid & 3;
    // B cp.async mapping: 32 f-rows x 32 chunks of 16B = 1024 chunks / 128 thr
    const int b_row0 = tid >> 5;     // idx>>5 with idx=tid+i*128
    const int b_cb   = tid & 31;

    auto load_stage = [&](int s, int k) {
        const int k0 = k * KC;
        const uint32_t sa  = sbase + s * STAGE_BYTES;
        const uint32_t sbr = sa + A_STAGE_BYTES;
#pragma unroll
        for (int i = 0; i < 4; i++) {
            int row = a_row + i * 32;
            CP_ASYNC16(sa + row * RSTRIDE_A + a_cb * 16,
                       Abase + (size_t)row * F_DIM + k0 + a_cb * 8);
        }
#pragma unroll
        for (int i = 0; i < 8; i++) {
            int row = b_row0 + i * 4;                  // f within chunk
            size_t gidx = (size_t)(k0 + row) * L_DIM + l0 + b_cb * 4;
            uint32_t sz = ((size_t)b * F_DIM * L_DIM + gidx + 4 <= xtotal)
                              ? 16u : 0u;
            CP_ASYNC16_SZ(sbr + row * BRAW_ROW_BYTES + b_cb * 16, Xb + gidx, sz);
        }
        CP_COMMIT();
    };

    load_stage(0, 0);
    load_stage(1, 1);

    const int lrow = lid & 15;
    const int lchunk = (lid >> 4) * 16;
    // conversion per-lane coords: 16 iters, f = 2j + (lid>>4), 4 floats each
    const int cv_fh = lid >> 4;          // 0..1
    const int cv_l4 = (lid & 15) * 4;    // 0..60

    for (int k = 0; k < KITERS; k++) {
        CP_WAIT(1);                  // stage k resident
        __syncthreads();             // all warps done with stage (k-1)'s slots
        if (k + 2 < KITERS) load_stage((k + 2) % STAGES, k + 2);

        const uint32_t sa  = sbase + (k % STAGES) * STAGE_BYTES;
        const uint32_t sbr = sa + A_STAGE_BYTES;

        // ---- convert Braw fp32 -> Bh fp16 (warp covers its 64 l-cols) ----
#pragma unroll
        for (int j = 0; j < 16; j++) {
            const int f  = 2 * j + cv_fh;
            const int lc = wn * 64 + cv_l4;
            float4 v = *reinterpret_cast<const float4*>(
                smem + (sbr - sbase) + f * BRAW_ROW_BYTES + lc * 4);
            __half2 h0 = __floats2half2_rn(v.x, v.y);
            __half2 h1 = __floats2half2_rn(v.z, v.w);
            uint32_t u0 = *reinterpret_cast<uint32_t*>(&h0);
            uint32_t u1 = *reinterpret_cast<uint32_t*>(&h1);
            asm volatile("st.shared.v2.b32 [%0], {%1, %2};"
                         :: "r"(sbh + f * BH_STRIDE + lc * 2), "r"(u0), "r"(u1)
                         : "memory");
        }
        __syncwarp();

        // ---- fragments + MMA ----
#pragma unroll
        for (int kk = 0; kk < 2; kk++) {
            const uint32_t koff = kk * 32 + lchunk;
            uint32_t af[4][4];
#pragma unroll
            for (int mi = 0; mi < 4; mi++) {
                uint32_t addr = sa + (wm * 64 + mi * 16 + lrow) * RSTRIDE_A + koff;
                LDSM_X4(af[mi][0], af[mi][1], af[mi][2], af[mi][3], addr);
            }
            uint32_t bf[8][2];
#pragma unroll
            for (int p = 0; p < 4; p++) {
                // trans: rows = f(k), lanes 0-15 -> k rows, lanes 16-31 -> n+8
                uint32_t addr = sbh + (kk * 16 + lrow) * BH_STRIDE
                                + wn * 128 + p * 32 + lchunk;
                uint32_t m0, m1, m2, m3;
                LDSM_X4_T(m0, m1, m2, m3, addr);
                bf[2 * p][0] = m0; bf[2 * p][1] = m1;
                bf[2 * p + 1][0] = m2; bf[2 * p + 1][1] = m3;
            }
#pragma unroll
            for (int mi = 0; mi < 4; mi++)
#pragma unroll
                for (int ni = 0; ni < 8; ni++)
                    mma_f16(d[mi][ni], af[mi][0], af[mi][1], af[mi][2], af[mi][3],
                            bf[ni][0], bf[ni][1]);
        }
    }

    // ---- epilogue: direct global float2 stores ----
#pragma unroll
    for (int mi = 0; mi < 4; mi++) {
        const int row = n0 + wm * 64 + mi * 16 + g;
        float* r0 = out + ((size_t)b * N_DIM + row) * L_DIM;
        float* r1 = r0 + 8 * L_DIM;
#pragma unroll
        for (int ni = 0; ni < 8; ni++) {
            const int l = l0 + wn * 64 + ni * 8 + 2 * t;
            if (l < L_DIM) {
                *reinterpret_cast<float2*>(r0 + l) =
                    make_float2(d[mi][ni][0], d[mi][ni][1]);
                *reinterpret_cast<float2*>(r1 + l) =
                    make_float2(d[mi][ni][2], d[mi][ni][3]);
            }
        }
    }
}

// ============================================================================
// host
// ============================================================================
extern "C" void kernel_launch(void* const* d_in, const int* in_sizes, int n_in,
                              void* d_out, int out_size) {
    const float* X = (const float*)d_in[0];
    const float* C = (const float*)d_in[1];
    const float* W = (const float*)d_in[2];
    for (int i = 0; i < n_in; i++) {
        if (in_sizes[i] == B_DIM * F_DIM * L_DIM) X = (const float*)d_in[i];
        else if (in_sizes[i] == F_DIM * N_DIM)    C = (const float*)d_in[i];
        else if (in_sizes[i] == N_DIM)            W = (const float*)d_in[i];
    }

    cudaFuncSetAttribute(gemm_kernel,
                         cudaFuncAttributeMaxDynamicSharedMemorySize, SMEM_BYTES);

    prep_a_kernel<<<dim3(N_DIM / 32, F_DIM / 32), dim3(32, 8)>>>(C, W);
    gemm_kernel<<<dim3(N_DIM / TM, LPAD / TN, B_DIM), 128, SMEM_BYTES>>>(
        (float*)d_out, X);
}

// round 12
// speedup vs baseline: 1.0370x; 1.0370x over previous
#include <cuda_runtime.h>
#include <cuda_fp16.h>
#include <cstdint>

// ============================================================================
// dims
// ============================================================================
#define B_DIM 32
#define F_DIM 1024
#define L_DIM 1000
#define N_DIM 2048
#define LPAD  1024

// GEMM tiling (per batch: M=N_DIM rows n, N=L cols l, K=F)
#define TM 128
#define TN 128
#define KC 32                    // K (f) per chunk
#define KITERS (F_DIM / KC)      // 32
#define SA 3                     // A fp16 stages   (prefetch distance 2)
#define SR 4                     // raw fp32 stages (prefetch distance 3)

// SMEM layout
#define RSTRIDE_A 80
#define A_STAGE_BYTES (TM * RSTRIDE_A)                     // 10240
#define BRAW_ROW_BYTES 512
#define BRAW_STAGE_BYTES (KC * BRAW_ROW_BYTES)             // 16384
#define RAW_OFF (SA * A_STAGE_BYTES)                       // 30720
#define BH_STRIDE 272
#define BH_BYTES (KC * BH_STRIDE)                          // 8704
#define BH_OFF (RAW_OFF + SR * BRAW_STAGE_BYTES)           // 96256
#define SMEM_BYTES (BH_OFF + 2 * BH_BYTES)                 // 113664 (2 CTAs/SM)

// ============================================================================
// device scratch (static globals: allocation-guard safe)
// ============================================================================
__device__ __align__(1024) __half g_A[(size_t)N_DIM * F_DIM];   // 4 MB

// ============================================================================
// helpers
// ============================================================================
__device__ __forceinline__ uint32_t smem_u32(const void* p) {
    uint32_t a;
    asm("{ .reg .u64 t; cvta.to.shared.u64 t, %1; cvt.u32.u64 %0, t; }"
        : "=r"(a) : "l"(p));
    return a;
}

#define CP_ASYNC16(dst, src) \
    asm volatile("cp.async.cg.shared.global [%0], [%1], 16;" \
                 :: "r"(dst), "l"(src) : "memory")
#define CP_ASYNC16_SZ(dst, src, sz) \
    asm volatile("cp.async.cg.shared.global [%0], [%1], 16, %2;" \
                 :: "r"(dst), "l"(src), "r"(sz) : "memory")
#define CP_COMMIT() asm volatile("cp.async.commit_group;" ::: "memory")
#define CP_WAIT(n)  asm volatile("cp.async.wait_group %0;" :: "n"(n) : "memory")

#define LDSM_X4(r0, r1, r2, r3, addr) \
    asm volatile("ldmatrix.sync.aligned.m8n8.x4.shared.b16 {%0,%1,%2,%3}, [%4];" \
                 : "=r"(r0), "=r"(r1), "=r"(r2), "=r"(r3) : "r"(addr))
#define LDSM_X4_T(r0, r1, r2, r3, addr) \
    asm volatile("ldmatrix.sync.aligned.m8n8.x4.trans.shared.b16 {%0,%1,%2,%3}, [%4];" \
                 : "=r"(r0), "=r"(r1), "=r"(r2), "=r"(r3) : "r"(addr))

__device__ __forceinline__ void mma_f16(float d[4],
                                        uint32_t a0, uint32_t a1,
                                        uint32_t a2, uint32_t a3,
                                        uint32_t b0, uint32_t b1) {
    asm volatile(
        "mma.sync.aligned.m16n8k16.row.col.f32.f16.f16.f32 "
        "{%0, %1, %2, %3}, {%4, %5, %6, %7}, {%8, %9}, {%0, %1, %2, %3};"
        : "+f"(d[0]), "+f"(d[1]), "+f"(d[2]), "+f"(d[3])
        : "r"(a0), "r"(a1), "r"(a2), "r"(a3), "r"(b0), "r"(b1));
}

// ============================================================================
// prep: A[n][f] = fp16(C[f][n] * W[n])
// ============================================================================
__global__ void prep_a_kernel(const float* __restrict__ C,
                              const float* __restrict__ W) {
    __shared__ float tile[32][33];
    const int n0 = blockIdx.x * 32;
    const int f0 = blockIdx.y * 32;
    const int tx = threadIdx.x, ty = threadIdx.y;
    const float w = W[n0 + tx];
#pragma unroll
    for (int i = 0; i < 32; i += 8)
        tile[ty + i][tx] = C[(size_t)(f0 + ty + i) * N_DIM + n0 + tx] * w;
    __syncthreads();
    if (tx < 16) {
#pragma unroll
        for (int i = 0; i < 32; i += 8) {
            const int n = n0 + ty + i;
            __half2 v = __floats2half2_rn(tile[2 * tx][ty + i],
                                          tile[2 * tx + 1][ty + i]);
            *reinterpret_cast<__half2*>(g_A + (size_t)n * F_DIM + f0 + 2 * tx) = v;
        }
    }
}

// ============================================================================
// fused GEMM: out[b, n0:+128, l0:+128] = A x X^T  (X fp32 converted in-flight;
// convert pipelined one chunk ahead; wait -> syncthreads -> read everywhere)
//   128 threads = 4 warps: 2(m) x 2(n), warp tile 64 x 64, 2 CTAs/SM
// ============================================================================
__global__ void __launch_bounds__(128, 2)
gemm_kernel(float* __restrict__ out, const float* __restrict__ X) {
    extern __shared__ __align__(128) char smem[];
    const uint32_t sbase = smem_u32(smem);
    const uint32_t sbh = sbase + BH_OFF;

    const int tid = threadIdx.x;
    const int wid = tid >> 5;
    const int lid = tid & 31;
    const int g = lid >> 2;
    const int t = lid & 3;

    const int wm = wid & 1;
    const int wn = wid >> 1;

    const int n0 = blockIdx.x * TM;
    const int l0 = blockIdx.y * TN;
    const int b  = blockIdx.z;

    const __half* Abase = g_A + (size_t)n0 * F_DIM;
    const float*  Xb    = X + (size_t)b * F_DIM * L_DIM;
    const size_t  xtotal = (size_t)B_DIM * F_DIM * L_DIM;

    float d[4][8][4];
#pragma unroll
    for (int mi = 0; mi < 4; mi++)
#pragma unroll
        for (int ni = 0; ni < 8; ni++)
#pragma unroll
            for (int r = 0; r < 4; r++) d[mi][ni][r] = 0.0f;

    // A cp.async: 128 rows x 4 chunks of 16B
    const int a_row = tid >> 2;
    const int a_cb  = tid & 3;
    // raw B cp.async: 32 f-rows x 32 chunks of 16B
    const int b_row0 = tid >> 5;
    const int b_cb   = tid & 31;

    auto load_A = [&](int k) {            // -> A stage k%SA
        const uint32_t sa = sbase + (k % SA) * A_STAGE_BYTES;
        const int k0 = k * KC;
#pragma unroll
        for (int i = 0; i < 4; i++) {
            int row = a_row + i * 32;
            CP_ASYNC16(sa + row * RSTRIDE_A + a_cb * 16,
                       Abase + (size_t)row * F_DIM + k0 + a_cb * 8);
        }
    };
    auto load_R = [&](int k) {            // -> raw stage k%SR
        const uint32_t sr = sbase + RAW_OFF + (k % SR) * BRAW_STAGE_BYTES;
        const int k0 = k * KC;
#pragma unroll
        for (int i = 0; i < 8; i++) {
            int row = b_row0 + i * 4;
            size_t gidx = (size_t)(k0 + row) * L_DIM + l0 + b_cb * 4;
            uint32_t sz = ((size_t)b * F_DIM * L_DIM + gidx + 4 <= xtotal)
                              ? 16u : 0u;
            CP_ASYNC16_SZ(sr + row * BRAW_ROW_BYTES + b_cb * 16, Xb + gidx, sz);
        }
    };

    // convert raw chunk k -> Bh[k&1] (warp covers its own 64 l-cols)
    const int cv_fh = lid >> 4;
    const int cv_l4 = (lid & 15) * 4;
    auto convert = [&](int k) {
        const uint32_t sr = sbase + RAW_OFF + (k % SR) * BRAW_STAGE_BYTES;
        const uint32_t dst = sbh + (k & 1) * BH_BYTES;
        const int lc = wn * 64 + cv_l4;
#pragma unroll
        for (int j = 0; j < 16; j++) {
            const int f = 2 * j + cv_fh;
            float4 v;
            asm volatile("ld.shared.v4.f32 {%0,%1,%2,%3}, [%4];"
                         : "=f"(v.x), "=f"(v.y), "=f"(v.z), "=f"(v.w)
                         : "r"(sr + f * BRAW_ROW_BYTES + lc * 4));
            __half2 h0 = __floats2half2_rn(v.x, v.y);
            __half2 h1 = __floats2half2_rn(v.z, v.w);
            uint32_t u0 = *reinterpret_cast<uint32_t*>(&h0);
            uint32_t u1 = *reinterpret_cast<uint32_t*>(&h1);
            asm volatile("st.shared.v2.b32 [%0], {%1, %2};"
                         :: "r"(dst + f * BH_STRIDE + lc * 2), "r"(u0), "r"(u1)
                         : "memory");
        }
    };

    // ---- prologue ----
    // commit1 = {A0, R0}, commit2 = {A1, R1}, commit3 = {R2}
    load_A(0); load_R(0); CP_COMMIT();
    load_A(1); load_R(1); CP_COMMIT();
    load_R(2);            CP_COMMIT();
    CP_WAIT(2);                  // commit1 done: A0, R0 resident (own)
    __syncthreads();             // cross-thread visibility
    convert(0);                  // Bh[0] <- raw chunk 0

    const int lrow = lid & 15;
    const int lchunk = (lid >> 4) * 16;

    // invariants at iter k top: commits = 3+k; CP_WAIT(1) -> A<=k, R<=k+1 done
    for (int k = 0; k < KITERS; k++) {
        CP_WAIT(1);
        __syncthreads();         // waits done everywhere; iter k-1 readers drained

        if (k + 1 < KITERS) convert(k + 1);          // Bh[(k+1)&1], no consumer now
        if (k + 2 < KITERS) load_A(k + 2);           // stage (k-1)%SA, readers drained
        if (k + 3 < KITERS) load_R(k + 3);           // stage (k-1)%SR, readers drained
        CP_COMMIT();                                 // exactly one group per iter

        const uint32_t sa  = sbase + (k % SA) * A_STAGE_BYTES;
        const uint32_t bhk = sbh + (k & 1) * BH_BYTES;

#pragma unroll
        for (int kk = 0; kk < 2; kk++) {
            const uint32_t koff = kk * 32 + lchunk;
            uint32_t af[4][4];
#pragma unroll
            for (int mi = 0; mi < 4; mi++) {
                uint32_t addr = sa + (wm * 64 + mi * 16 + lrow) * RSTRIDE_A + koff;
                LDSM_X4(af[mi][0], af[mi][1], af[mi][2], af[mi][3], addr);
            }
            uint32_t bf[8][2];
#pragma unroll
            for (int p = 0; p < 4; p++) {
                uint32_t addr = bhk + (kk * 16 + lrow) * BH_STRIDE
                                + wn * 128 + p * 32 + lchunk;
                uint32_t m0, m1, m2, m3;
                LDSM_X4_T(m0, m1, m2, m3, addr);
                bf[2 * p][0] = m0; bf[2 * p][1] = m1;
                bf[2 * p + 1][0] = m2; bf[2 * p + 1][1] = m3;
            }
#pragma unroll
            for (int mi = 0; mi < 4; mi++)
#pragma unroll
                for (int ni = 0; ni < 8; ni++)
                    mma_f16(d[mi][ni], af[mi][0], af[mi][1], af[mi][2], af[mi][3],
                            bf[ni][0], bf[ni][1]);
        }
    }

    // ---- epilogue: direct global float2 stores ----
#pragma unroll
    for (int mi = 0; mi < 4; mi++) {
        const int row = n0 + wm * 64 + mi * 16 + g;
        float* r0 = out + ((size_t)b * N_DIM + row) * L_DIM;
        float* r1 = r0 + 8 * L_DIM;
#pragma unroll
        for (int ni = 0; ni < 8; ni++) {
            const int l = l0 + wn * 64 + ni * 8 + 2 * t;
            if (l < L_DIM) {
                *reinterpret_cast<float2*>(r0 + l) =
                    make_float2(d[mi][ni][0], d[mi][ni][1]);
                *reinterpret_cast<float2*>(r1 + l) =
                    make_float2(d[mi][ni][2], d[mi][ni][3]);
            }
        }
    }
}

// ============================================================================
// host
// ============================================================================
extern "C" void kernel_launch(void* const* d_in, const int* in_sizes, int n_in,
                              void* d_out, int out_size) {
    const float* X = (const float*)d_in[0];
    const float* C = (const float*)d_in[1];
    const float* W = (const float*)d_in[2];
    for (int i = 0; i < n_in; i++) {
        if (in_sizes[i] == B_DIM * F_DIM * L_DIM) X = (const float*)d_in[i];
        else if (in_sizes[i] == F_DIM * N_DIM)    C = (const float*)d_in[i];
        else if (in_sizes[i] == N_DIM)            W = (const float*)d_in[i];
    }

    cudaFuncSetAttribute(gemm_kernel,
                         cudaFuncAttributeMaxDynamicSharedMemorySize, SMEM_BYTES);

    prep_a_kernel<<<dim3(N_DIM / 32, F_DIM / 32), dim3(32, 8)>>>(C, W);
    gemm_kernel<<<dim3(N_DIM / TM, LPAD / TN, B_DIM), 128, SMEM_BYTES>>>(
        (float*)d_out, X);
}

// round 13
// speedup vs baseline: 1.1069x; 1.0674x over previous
#include <cuda_runtime.h>
#include <cuda_fp16.h>
#include <cstdint>

// ============================================================================
// dims
// ============================================================================
#define B_DIM 32
#define F_DIM 1024
#define L_DIM 1000
#define N_DIM 2048
#define LPAD  1024

// GEMM tiling (per batch: M=N_DIM rows n, N=L cols l, K=F)
#define TM 128
#define TN 128
#define KC 32                    // K (f) per chunk
#define KITERS (F_DIM / KC)      // 32
#define SA 3                     // A fp16 stages (prefetch distance 2)

// SMEM layout: A stages + double-buffered Bh fp16 [f 32][l 128]
#define RSTRIDE_A 80
#define A_STAGE_BYTES (TM * RSTRIDE_A)                     // 10240
#define BH_STRIDE 272
#define BH_BYTES (KC * BH_STRIDE)                          // 8704
#define BH_OFF (SA * A_STAGE_BYTES)                        // 30720
#define SMEM_BYTES (BH_OFF + 2 * BH_BYTES)                 // 48128 (2 CTAs/SM)

// ============================================================================
// device scratch (static globals: allocation-guard safe)
// ============================================================================
__device__ __align__(1024) __half g_A[(size_t)N_DIM * F_DIM];   // 4 MB

// ============================================================================
// helpers
// ============================================================================
__device__ __forceinline__ uint32_t smem_u32(const void* p) {
    uint32_t a;
    asm("{ .reg .u64 t; cvta.to.shared.u64 t, %1; cvt.u32.u64 %0, t; }"
        : "=r"(a) : "l"(p));
    return a;
}

#define CP_ASYNC16(dst, src) \
    asm volatile("cp.async.cg.shared.global [%0], [%1], 16;" \
                 :: "r"(dst), "l"(src) : "memory")
#define CP_COMMIT() asm volatile("cp.async.commit_group;" ::: "memory")
#define CP_WAIT(n)  asm volatile("cp.async.wait_group %0;" :: "n"(n) : "memory")

#define LDSM_X4(r0, r1, r2, r3, addr) \
    asm volatile("ldmatrix.sync.aligned.m8n8.x4.shared.b16 {%0,%1,%2,%3}, [%4];" \
                 : "=r"(r0), "=r"(r1), "=r"(r2), "=r"(r3) : "r"(addr))
#define LDSM_X4_T(r0, r1, r2, r3, addr) \
    asm volatile("ldmatrix.sync.aligned.m8n8.x4.trans.shared.b16 {%0,%1,%2,%3}, [%4];" \
                 : "=r"(r0), "=r"(r1), "=r"(r2), "=r"(r3) : "r"(addr))

__device__ __forceinline__ void mma_f16(float d[4],
                                        uint32_t a0, uint32_t a1,
                                        uint32_t a2, uint32_t a3,
                                        uint32_t b0, uint32_t b1) {
    asm volatile(
        "mma.sync.aligned.m16n8k16.row.col.f32.f16.f16.f32 "
        "{%0, %1, %2, %3}, {%4, %5, %6, %7}, {%8, %9}, {%0, %1, %2, %3};"
        : "+f"(d[0]), "+f"(d[1]), "+f"(d[2]), "+f"(d[3])
        : "r"(a0), "r"(a1), "r"(a2), "r"(a3), "r"(b0), "r"(b1));
}

// ============================================================================
// prep: A[n][f] = fp16(C[f][n] * W[n])
// ============================================================================
__global__ void prep_a_kernel(const float* __restrict__ C,
                              const float* __restrict__ W) {
    __shared__ float tile[32][33];
    const int n0 = blockIdx.x * 32;
    const int f0 = blockIdx.y * 32;
    const int tx = threadIdx.x, ty = threadIdx.y;
    const float w = W[n0 + tx];
#pragma unroll
    for (int i = 0; i < 32; i += 8)
        tile[ty + i][tx] = C[(size_t)(f0 + ty + i) * N_DIM + n0 + tx] * w;
    __syncthreads();
    if (tx < 16) {
#pragma unroll
        for (int i = 0; i < 32; i += 8) {
            const int n = n0 + ty + i;
            __half2 v = __floats2half2_rn(tile[2 * tx][ty + i],
                                          tile[2 * tx + 1][ty + i]);
            *reinterpret_cast<__half2*>(g_A + (size_t)n * F_DIM + f0 + 2 * tx) = v;
        }
    }
}

// ============================================================================
// fused GEMM: out[b, n0:+128, l0:+128] = A x X^T
//   X converted fp32->fp16 in REGISTERS from global (lane = f-row, warp owns
//   its 32 l-cols: no duplication, no raw smem stage, no X-path sync).
//   128 threads = 4 warps: 2(m) x 2(n), warp tile 64 x 64, 2 CTAs/SM
// ============================================================================
__global__ void __launch_bounds__(128, 2)
gemm_kernel(float* __restrict__ out, const float* __restrict__ X) {
    extern __shared__ __align__(128) char smem[];
    const uint32_t sbase = smem_u32(smem);
    const uint32_t sbh = sbase + BH_OFF;

    const int tid = threadIdx.x;
    const int wid = tid >> 5;
    const int lid = tid & 31;
    const int g = lid >> 2;
    const int t = lid & 3;

    const int wm = wid & 1;
    const int wn = wid >> 1;

    const int n0 = blockIdx.x * TM;
    const int l0 = blockIdx.y * TN;
    const int b  = blockIdx.z;

    const __half* Abase = g_A + (size_t)n0 * F_DIM;
    const float*  Xb    = X + (size_t)b * F_DIM * L_DIM;

    float d[4][8][4];
#pragma unroll
    for (int mi = 0; mi < 4; mi++)
#pragma unroll
        for (int ni = 0; ni < 8; ni++)
#pragma unroll
            for (int r = 0; r < 4; r++) d[mi][ni][r] = 0.0f;

    // A cp.async: 128 rows x 4 chunks of 16B
    const int a_row = tid >> 2;
    const int a_cb  = tid & 3;
    auto load_A = [&](int k) {
        const uint32_t sa = sbase + (k % SA) * A_STAGE_BYTES;
        const int k0 = k * KC;
#pragma unroll
        for (int i = 0; i < 4; i++) {
            int row = a_row + i * 32;
            CP_ASYNC16(sa + row * RSTRIDE_A + a_cb * 16,
                       Abase + (size_t)row * F_DIM + k0 + a_cb * 8);
        }
    };

    // X register path: lane lid = f-row (k*32+lid); warp wid owns l-cols
    // [l0 + 32*wid, +32) = 8 float4 per thread. L_DIM % 4 == 0 -> no straddle.
    const int xl0 = l0 + wid * 32;
    float4 xr[8];
    auto load_X = [&](int k) {
        const float* src = Xb + (size_t)(k * KC + lid) * L_DIM;
#pragma unroll
        for (int c = 0; c < 8; c++) {
            const int idx = xl0 + c * 4;
            xr[c] = (idx + 3 < L_DIM)
                        ? *reinterpret_cast<const float4*>(src + idx)
                        : make_float4(0.f, 0.f, 0.f, 0.f);
        }
    };
    // convert regs (chunk k data) -> Bh[k&1]; row f=lid, cols 32*wid..+31
    auto sts_convert = [&](int k) {
        const uint32_t dst = sbh + (k & 1) * BH_BYTES
                             + lid * BH_STRIDE + wid * 64;
#pragma unroll
        for (int c = 0; c < 4; c++) {
            __half2 h0 = __floats2half2_rn(xr[2 * c].x, xr[2 * c].y);
            __half2 h1 = __floats2half2_rn(xr[2 * c].z, xr[2 * c].w);
            __half2 h2 = __floats2half2_rn(xr[2 * c + 1].x, xr[2 * c + 1].y);
            __half2 h3 = __floats2half2_rn(xr[2 * c + 1].z, xr[2 * c + 1].w);
            asm volatile("st.shared.v4.b32 [%0], {%1, %2, %3, %4};"
                         :: "r"(dst + c * 16),
                            "r"(*reinterpret_cast<uint32_t*>(&h0)),
                            "r"(*reinterpret_cast<uint32_t*>(&h1)),
                            "r"(*reinterpret_cast<uint32_t*>(&h2)),
                            "r"(*reinterpret_cast<uint32_t*>(&h3))
                         : "memory");
        }
    };

    // ---- prologue ----
    load_X(0);                    // regs <- chunk 0
    load_A(0); CP_COMMIT();
    load_A(1); CP_COMMIT();
    sts_convert(0);               // Bh[0] <- chunk 0 (own regs, no sync needed)
    load_X(1);                    // regs <- chunk 1

    const int lrow = lid & 15;
    const int lchunk = (lid >> 4) * 16;

    // iter k top: commits = 2+k -> CP_WAIT(1) => A stages <= k resident
    for (int k = 0; k < KITERS; k++) {
        CP_WAIT(1);
        __syncthreads();          // publishes STS(chunk k); drains Bh[(k+1)&1] readers

        if (k + 1 < KITERS) sts_convert(k + 1);   // Bh[(k+1)&1] <- regs
        if (k + 2 < KITERS) load_X(k + 2);        // regs <- chunk k+2 (LDG)
        if (k + 2 < KITERS) load_A(k + 2);        // A stage (k-1)%SA, readers drained
        CP_COMMIT();                              // exactly one group per iter

        const uint32_t sa  = sbase + (k % SA) * A_STAGE_BYTES;
        const uint32_t bhk = sbh + (k & 1) * BH_BYTES;

#pragma unroll
        for (int kk = 0; kk < 2; kk++) {
            const uint32_t koff = kk * 32 + lchunk;
            uint32_t af[4][4];
#pragma unroll
            for (int mi = 0; mi < 4; mi++) {
                uint32_t addr = sa + (wm * 64 + mi * 16 + lrow) * RSTRIDE_A + koff;
                LDSM_X4(af[mi][0], af[mi][1], af[mi][2], af[mi][3], addr);
            }
            uint32_t bf[8][2];
#pragma unroll
            for (int p = 0; p < 4; p++) {
                uint32_t addr = bhk + (kk * 16 + lrow) * BH_STRIDE
                                + wn * 128 + p * 32 + lchunk;
                uint32_t m0, m1, m2, m3;
                LDSM_X4_T(m0, m1, m2, m3, addr);
                bf[2 * p][0] = m0; bf[2 * p][1] = m1;
                bf[2 * p + 1][0] = m2; bf[2 * p + 1][1] = m3;
            }
#pragma unroll
            for (int mi = 0; mi < 4; mi++)
#pragma unroll
                for (int ni = 0; ni < 8; ni++)
                    mma_f16(d[mi][ni], af[mi][0], af[mi][1], af[mi][2], af[mi][3],
                            bf[ni][0], bf[ni][1]);
        }
    }

    // ---- epilogue: direct global float2 stores ----
#pragma unroll
    for (int mi = 0; mi < 4; mi++) {
        const int row = n0 + wm * 64 + mi * 16 + g;
        float* r0 = out + ((size_t)b * N_DIM + row) * L_DIM;
        float* r1 = r0 + 8 * L_DIM;
#pragma unroll
        for (int ni = 0; ni < 8; ni++) {
            const int l = l0 + wn * 64 + ni * 8 + 2 * t;
            if (l < L_DIM) {
                *reinterpret_cast<float2*>(r0 + l) =
                    make_float2(d[mi][ni][0], d[mi][ni][1]);
                *reinterpret_cast<float2*>(r1 + l) =
                    make_float2(d[mi][ni][2], d[mi][ni][3]);
            }
        }
    }
}

// ============================================================================
// host
// ============================================================================
extern "C" void kernel_launch(void* const* d_in, const int* in_sizes, int n_in,
                              void* d_out, int out_size) {
    const float* X = (const float*)d_in[0];
    const float* C = (const float*)d_in[1];
    const float* W = (const float*)d_in[2];
    for (int i = 0; i < n_in; i++) {
        if (in_sizes[i] == B_DIM * F_DIM * L_DIM) X = (const float*)d_in[i];
        else if (in_sizes[i] == F_DIM * N_DIM)    C = (const float*)d_in[i];
        else if (in_sizes[i] == N_DIM)            W = (const float*)d_in[i];
    }

    cudaFuncSetAttribute(gemm_kernel,
                         cudaFuncAttributeMaxDynamicSharedMemorySize, SMEM_BYTES);

    prep_a_kernel<<<dim3(N_DIM / 32, F_DIM / 32), dim3(32, 8)>>>(C, W);
    gemm_kernel<<<dim3(N_DIM / TM, LPAD / TN, B_DIM), 128, SMEM_BYTES>>>(
        (float*)d_out, X);
}

// round 14
// speedup vs baseline: 1.2478x; 1.1272x over previous
#include <cuda_runtime.h>
#include <cuda_fp16.h>
#include <cstdint>

// ============================================================================
// dims
// ============================================================================
#define B_DIM 32
#define F_DIM 1024
#define L_DIM 1000
#define N_DIM 2048
#define LPAD  1024

// GEMM tiling (per batch: M=N_DIM rows n, N=L cols l, K=F)
#define TM 128
#define TN 128
#define KC 32                    // K halves per stage (64B rows)
#define STAGES 4
#define KITERS (F_DIM / KC)      // 32

// SMEM: padded row stride 40 halves = 80B -> ldmatrix conflict-free
#define RSTRIDE_B 80
#define A_STAGE_BYTES (TM * RSTRIDE_B)                     // 10240
#define B_STAGE_BYTES (TN * RSTRIDE_B)                     // 10240
#define STAGE_BYTES (A_STAGE_BYTES + B_STAGE_BYTES)        // 20480
#define SMEM_BYTES (STAGES * STAGE_BYTES)                  // 81920 (2 CTAs/SM)

// ============================================================================
// device scratch (static globals: allocation-guard safe)
// ============================================================================
__device__ __align__(1024) __half g_A [(size_t)N_DIM * F_DIM];        // 4 MB
__device__ __align__(1024) __half g_Xt[(size_t)B_DIM * LPAD * F_DIM]; // 67 MB

// ============================================================================
// helpers
// ============================================================================
__device__ __forceinline__ uint32_t smem_u32(const void* p) {
    uint32_t a;
    asm("{ .reg .u64 t; cvta.to.shared.u64 t, %1; cvt.u32.u64 %0, t; }"
        : "=r"(a) : "l"(p));
    return a;
}

#define CP_ASYNC16(dst, src) \
    asm volatile("cp.async.cg.shared.global [%0], [%1], 16;" \
                 :: "r"(dst), "l"(src) : "memory")
#define CP_COMMIT() asm volatile("cp.async.commit_group;" ::: "memory")
#define CP_WAIT(n)  asm volatile("cp.async.wait_group %0;" :: "n"(n) : "memory")

#define LDSM_X4(r0, r1, r2, r3, addr) \
    asm volatile("ldmatrix.sync.aligned.m8n8.x4.shared.b16 {%0,%1,%2,%3}, [%4];" \
                 : "=r"(r0), "=r"(r1), "=r"(r2), "=r"(r3) : "r"(addr))

__device__ __forceinline__ void mma_f16(float d[4],
                                        uint32_t a0, uint32_t a1,
                                        uint32_t a2, uint32_t a3,
                                        uint32_t b0, uint32_t b1) {
    asm volatile(
        "mma.sync.aligned.m16n8k16.row.col.f32.f16.f16.f32 "
        "{%0, %1, %2, %3}, {%4, %5, %6, %7}, {%8, %9}, {%0, %1, %2, %3};"
        : "+f"(d[0]), "+f"(d[1]), "+f"(d[2]), "+f"(d[3])
        : "r"(a0), "r"(a1), "r"(a2), "r"(a3), "r"(b0), "r"(b1));
}

// ============================================================================
// prep 1: A[n][f] = fp16(C[f][n] * W[n])
// ============================================================================
__global__ void prep_a_kernel(const float* __restrict__ C,
                              const float* __restrict__ W) {
    __shared__ float tile[32][33];
    const int n0 = blockIdx.x * 32;
    const int f0 = blockIdx.y * 32;
    const int tx = threadIdx.x, ty = threadIdx.y;
    const float w = W[n0 + tx];
#pragma unroll
    for (int i = 0; i < 32; i += 8)
        tile[ty + i][tx] = C[(size_t)(f0 + ty + i) * N_DIM + n0 + tx] * w;
    __syncthreads();
    if (tx < 16) {
#pragma unroll
        for (int i = 0; i < 32; i += 8) {
            const int n = n0 + ty + i;
            __half2 v = __floats2half2_rn(tile[2 * tx][ty + i],
                                          tile[2 * tx + 1][ty + i]);
            *reinterpret_cast<__half2*>(g_A + (size_t)n * F_DIM + f0 + 2 * tx) = v;
        }
    }
}

// ============================================================================
// prep 2: Xt[b][l][f] = fp16(X[b][f][l]); 64-f x 32-l tiles, 128B-coalesced
// ============================================================================
__global__ void prep_x_kernel(const float* __restrict__ X) {
    __shared__ float tile[64][33];
    const int l0 = blockIdx.x * 32;
    const int f0 = blockIdx.y * 64;
    const int b  = blockIdx.z;
    const int tx = threadIdx.x, ty = threadIdx.y;
    const int tid = ty * 32 + tx;
    const float* Xb = X + (size_t)b * F_DIM * L_DIM;
    const int l = l0 + tx;
#pragma unroll
    for (int i = 0; i < 64; i += 8)
        tile[ty + i][tx] = (l < L_DIM)
            ? Xb[(size_t)(f0 + ty + i) * L_DIM + l] : 0.0f;
    __syncthreads();

    const int row = tid >> 3;
    const int c8  = tid & 7;
    __half2 h[4];
#pragma unroll
    for (int m = 0; m < 4; m++)
        h[m] = __floats2half2_rn(tile[8 * c8 + 2 * m][row],
                                 tile[8 * c8 + 2 * m + 1][row]);
    __half* Xtb = g_Xt + (size_t)b * LPAD * F_DIM;
    *reinterpret_cast<int4*>(Xtb + (size_t)(l0 + row) * F_DIM + f0 + 8 * c8) =
        *reinterpret_cast<int4*>(h);
}

// ============================================================================
// GEMM: out[b, n0:+128, l0:+128] = A x Xt^T
//   256 threads = 8 warps: 2(m) x 4(n), warp tile 64 x 32 (64 accum regs),
//   mma m16n8k16 f16.f32, ldmatrix, 4-stage cp.async, 2 CTAs/SM = 16 warps/SM
// ============================================================================
__global__ void __launch_bounds__(256, 2)
gemm_kernel(float* __restrict__ out) {
    extern __shared__ __align__(128) char smem[];
    const uint32_t sbase = smem_u32(smem);

    const int tid = threadIdx.x;
    const int wid = tid >> 5;
    const int lid = tid & 31;
    const int g = lid >> 2;
    const int t = lid & 3;

    const int wm = wid & 1;          // 0..1 -> 64 m-rows each
    const int wn = wid >> 1;         // 0..3 -> 32 n-cols each

    const int n0 = blockIdx.x * TM;
    const int l0 = blockIdx.y * TN;
    const int b  = blockIdx.z;

    const __half* Abase = g_A  + (size_t)n0 * F_DIM;
    const __half* Bbase = g_Xt + ((size_t)b * LPAD + l0) * F_DIM;

    float d[4][4][4];                // mi<4 (m16), ni<4 (n8), 4 regs
#pragma unroll
    for (int mi = 0; mi < 4; mi++)
#pragma unroll
        for (int ni = 0; ni < 4; ni++)
#pragma unroll
            for (int r = 0; r < 4; r++) d[mi][ni][r] = 0.0f;

    // cp.async mapping: 256 threads cover 128 rows x 4 chunks (16B), 2 iters
    const int c_row = tid >> 2;      // 0..63, +64 per i
    const int c_cb  = tid & 3;

    auto load_stage = [&](int s, int k) {
        const int k0 = k * KC;
        const uint32_t sa = sbase + s * STAGE_BYTES;
        const uint32_t sb = sa + A_STAGE_BYTES;
#pragma unroll
        for (int i = 0; i < 2; i++) {
            int row = c_row + i * 64;
            CP_ASYNC16(sa + row * RSTRIDE_B + c_cb * 16,
                       Abase + (size_t)row * F_DIM + k0 + c_cb * 8);
        }
#pragma unroll
        for (int i = 0; i < 2; i++) {
            int row = c_row + i * 64;
            CP_ASYNC16(sb + row * RSTRIDE_B + c_cb * 16,
                       Bbase + (size_t)row * F_DIM + k0 + c_cb * 8);
        }
        CP_COMMIT();
    };

    // prologue: stages 0..2
    load_stage(0, 0);
    load_stage(1, 1);
    load_stage(2, 2);

    const int lrow = lid & 15;
    const int lchunk = (lid >> 4) * 16;

    for (int k = 0; k < KITERS; k++) {
        CP_WAIT(2);                  // stage k resident
        __syncthreads();             // all warps done with stage (k-1)%4
        if (k + 3 < KITERS) load_stage((k + 3) % STAGES, k + 3);

        const uint32_t sa = sbase + (k % STAGES) * STAGE_BYTES;
        const uint32_t sb = sa + A_STAGE_BYTES;

#pragma unroll
        for (int kk = 0; kk < 2; kk++) {
            const uint32_t koff = kk * 32 + lchunk;
            uint32_t af[4][4];
#pragma unroll
            for (int mi = 0; mi < 4; mi++) {
                uint32_t addr = sa + (wm * 64 + mi * 16 + lrow) * RSTRIDE_B + koff;
                LDSM_X4(af[mi][0], af[mi][1], af[mi][2], af[mi][3], addr);
            }
            uint32_t bf[4][2];
#pragma unroll
            for (int p = 0; p < 2; p++) {
                uint32_t addr = sb + (wn * 32 + p * 16 + lrow) * RSTRIDE_B + koff;
                uint32_t m0, m1, m2, m3;
                LDSM_X4(m0, m1, m2, m3, addr);
                bf[2 * p][0] = m0; bf[2 * p][1] = m2;
                bf[2 * p + 1][0] = m1; bf[2 * p + 1][1] = m3;
            }
#pragma unroll
            for (int mi = 0; mi < 4; mi++)
#pragma unroll
                for (int ni = 0; ni < 4; ni++)
                    mma_f16(d[mi][ni], af[mi][0], af[mi][1], af[mi][2], af[mi][3],
                            bf[ni][0], bf[ni][1]);
        }
    }

    // ---- epilogue: direct global float2 stores ----
#pragma unroll
    for (int mi = 0; mi < 4; mi++) {
        const int row = n0 + wm * 64 + mi * 16 + g;
        float* r0 = out + ((size_t)b * N_DIM + row) * L_DIM;
        float* r1 = r0 + 8 * L_DIM;
#pragma unroll
        for (int ni = 0; ni < 4; ni++) {
            const int l = l0 + wn * 32 + ni * 8 + 2 * t;
            if (l < L_DIM) {
                *reinterpret_cast<float2*>(r0 + l) =
                    make_float2(d[mi][ni][0], d[mi][ni][1]);
                *reinterpret_cast<float2*>(r1 + l) =
                    make_float2(d[mi][ni][2], d[mi][ni][3]);
            }
        }
    }
}

// ============================================================================
// host
// ============================================================================
extern "C" void kernel_launch(void* const* d_in, const int* in_sizes, int n_in,
                              void* d_out, int out_size) {
    const float* X = (const float*)d_in[0];
    const float* C = (const float*)d_in[1];
    const float* W = (const float*)d_in[2];
    for (int i = 0; i < n_in; i++) {
        if (in_sizes[i] == B_DIM * F_DIM * L_DIM) X = (const float*)d_in[i];
        else if (in_sizes[i] == F_DIM * N_DIM)    C = (const float*)d_in[i];
        else if (in_sizes[i] == N_DIM)            W = (const float*)d_in[i];
    }

    cudaFuncSetAttribute(gemm_kernel,
                         cudaFuncAttributeMaxDynamicSharedMemorySize, SMEM_BYTES);

    prep_a_kernel<<<dim3(N_DIM / 32, F_DIM / 32), dim3(32, 8)>>>(C, W);
    prep_x_kernel<<<dim3(LPAD / 32, F_DIM / 64, B_DIM), dim3(32, 8)>>>(X);
    gemm_kernel<<<dim3(N_DIM / TM, LPAD / TN, B_DIM), 256, SMEM_BYTES>>>(
        (float*)d_out);
}

// round 15
// speedup vs baseline: 1.2793x; 1.0253x over previous
#include <cuda_runtime.h>
#include <cuda_fp16.h>
#include <cstdint>

// ============================================================================
// dims
// ============================================================================
#define B_DIM 32
#define F_DIM 1024
#define L_DIM 1000
#define N_DIM 2048
#define LPAD  1024

// GEMM tiling (per batch: M=N_DIM rows n, N=L cols l, K=F)
#define TM 128
#define TN 128
#define KC 32                    // K halves per stage (64B rows)
#define STAGES 4
#define KITERS (F_DIM / KC)      // 32

// SMEM: padded row stride 40 halves = 80B -> ldmatrix conflict-free
#define RSTRIDE_B 80
#define A_STAGE_BYTES (TM * RSTRIDE_B)                     // 10240
#define B_STAGE_BYTES (TN * RSTRIDE_B)                     // 10240
#define STAGE_BYTES (A_STAGE_BYTES + B_STAGE_BYTES)        // 20480
#define SMEM_BYTES (STAGES * STAGE_BYTES)                  // 81920 (2 CTAs/SM)

// ============================================================================
// device scratch (static globals: allocation-guard safe)
// ============================================================================
__device__ __align__(1024) __half g_A [(size_t)N_DIM * F_DIM];        // 4 MB
__device__ __align__(1024) __half g_Xt[(size_t)B_DIM * LPAD * F_DIM]; // 67 MB

// ============================================================================
// helpers
// ============================================================================
__device__ __forceinline__ uint32_t smem_u32(const void* p) {
    uint32_t a;
    asm("{ .reg .u64 t; cvta.to.shared.u64 t, %1; cvt.u32.u64 %0, t; }"
        : "=r"(a) : "l"(p));
    return a;
}

#define CP_ASYNC16(dst, src) \
    asm volatile("cp.async.cg.shared.global [%0], [%1], 16;" \
                 :: "r"(dst), "l"(src) : "memory")
#define CP_COMMIT() asm volatile("cp.async.commit_group;" ::: "memory")
#define CP_WAIT(n)  asm volatile("cp.async.wait_group %0;" :: "n"(n) : "memory")

#define LDSM_X4(r0, r1, r2, r3, addr) \
    asm volatile("ldmatrix.sync.aligned.m8n8.x4.shared.b16 {%0,%1,%2,%3}, [%4];" \
                 : "=r"(r0), "=r"(r1), "=r"(r2), "=r"(r3) : "r"(addr))

__device__ __forceinline__ void mma_f16(float d[4],
                                        uint32_t a0, uint32_t a1,
                                        uint32_t a2, uint32_t a3,
                                        uint32_t b0, uint32_t b1) {
    asm volatile(
        "mma.sync.aligned.m16n8k16.row.col.f32.f16.f16.f32 "
        "{%0, %1, %2, %3}, {%4, %5, %6, %7}, {%8, %9}, {%0, %1, %2, %3};"
        : "+f"(d[0]), "+f"(d[1]), "+f"(d[2]), "+f"(d[3])
        : "r"(a0), "r"(a1), "r"(a2), "r"(a3), "r"(b0), "r"(b1));
}

// ============================================================================
// merged prep (one launch): z < FZ_X -> Xt tiles; z >= FZ_X -> A tiles
//   Xt part: Xt[b][l][f] = fp16(X[b][f][l]), grid (32 l-tiles, 16 f-tiles, 32 b)
//   A  part: A[n][f] = fp16(C[f][n] * W[n]),  64 n-tiles x 32 f-tiles folded in
// ============================================================================
#define PZ_X (B_DIM)                       // 32 z-slices for X (each 32x16 xy)
#define PZ_A (PZ_X + 2)                    // 2 z-slices for A (each 32x32 xy)

__global__ void prep_kernel(const float* __restrict__ X,
                            const float* __restrict__ C,
                            const float* __restrict__ W) {
    const int tx = threadIdx.x, ty = threadIdx.y;
    if (blockIdx.z < PZ_X) {
        // ---- X transpose+convert: 64-f x 32-l tile ----
        __shared__ float tile[64][33];
        const int l0 = blockIdx.x * 32;
        const int f0 = blockIdx.y * 64;
        const int b  = blockIdx.z;
        const int tid = ty * 32 + tx;
        const float* Xb = X + (size_t)b * F_DIM * L_DIM;
        const int l = l0 + tx;
#pragma unroll
        for (int i = 0; i < 64; i += 8)
            tile[ty + i][tx] = (l < L_DIM)
                ? Xb[(size_t)(f0 + ty + i) * L_DIM + l] : 0.0f;
        __syncthreads();
        const int row = tid >> 3;
        const int c8  = tid & 7;
        __half2 h[4];
#pragma unroll
        for (int m = 0; m < 4; m++)
            h[m] = __floats2half2_rn(tile[8 * c8 + 2 * m][row],
                                     tile[8 * c8 + 2 * m + 1][row]);
        __half* Xtb = g_Xt + (size_t)b * LPAD * F_DIM;
        *reinterpret_cast<int4*>(Xtb + (size_t)(l0 + row) * F_DIM + f0 + 8 * c8) =
            *reinterpret_cast<int4*>(h);
    } else {
        // ---- A build: 32x32 tile; z in {PZ_X, PZ_X+1} selects n-half ----
        __shared__ float tile[32][33];
        const int zi = blockIdx.z - PZ_X;          // 0..1
        // 2048 n-tiles-of-32 = 64; map: x (0..31) -> n-tile pairs, zi halves
        const int n0 = (blockIdx.x + zi * 32) * 32;
        const int f0 = blockIdx.y * 64;            // two 32-f subtiles below
        const float w = W[n0 + tx];
#pragma unroll
        for (int half = 0; half < 2; half++) {
            const int fh = f0 + half * 32;
#pragma unroll
            for (int i = 0; i < 32; i += 8)
                tile[ty + i][tx] = C[(size_t)(fh + ty + i) * N_DIM + n0 + tx] * w;
            __syncthreads();
            if (tx < 16) {
#pragma unroll
                for (int i = 0; i < 32; i += 8) {
                    const int n = n0 + ty + i;
                    __half2 v = __floats2half2_rn(tile[2 * tx][ty + i],
                                                  tile[2 * tx + 1][ty + i]);
                    *reinterpret_cast<__half2*>(
                        g_A + (size_t)n * F_DIM + fh + 2 * tx) = v;
                }
            }
            __syncthreads();
        }
    }
}

// ============================================================================
// GEMM: out[b, n0:+128, l0:+128] = A x Xt^T
//   256 threads = 8 warps: 2(m) x 4(n), warp tile 64 x 32 (64 accum regs),
//   B-fragment prefetch across kk; 4-stage cp.async; 2 CTAs/SM = 16 warps/SM
// ============================================================================
__global__ void __launch_bounds__(256, 2)
gemm_kernel(float* __restrict__ out) {
    extern __shared__ __align__(128) char smem[];
    const uint32_t sbase = smem_u32(smem);

    const int tid = threadIdx.x;
    const int wid = tid >> 5;
    const int lid = tid & 31;
    const int g = lid >> 2;
    const int t = lid & 3;

    const int wm = wid & 1;          // 0..1 -> 64 m-rows each
    const int wn = wid >> 1;         // 0..3 -> 32 n-cols each

    const int n0 = blockIdx.x * TM;
    const int l0 = blockIdx.y * TN;
    const int b  = blockIdx.z;

    const __half* Abase = g_A  + (size_t)n0 * F_DIM;
    const __half* Bbase = g_Xt + ((size_t)b * LPAD + l0) * F_DIM;

    float d[4][4][4];
#pragma unroll
    for (int mi = 0; mi < 4; mi++)
#pragma unroll
        for (int ni = 0; ni < 4; ni++)
#pragma unroll
            for (int r = 0; r < 4; r++) d[mi][ni][r] = 0.0f;

    const int c_row = tid >> 2;      // 0..63, +64 per i
    const int c_cb  = tid & 3;

    auto load_stage = [&](int s, int k) {
        const int k0 = k * KC;
        const uint32_t sa = sbase + s * STAGE_BYTES;
        const uint32_t sb = sa + A_STAGE_BYTES;
#pragma unroll
        for (int i = 0; i < 2; i++) {
            int row = c_row + i * 64;
            CP_ASYNC16(sa + row * RSTRIDE_B + c_cb * 16,
                       Abase + (size_t)row * F_DIM + k0 + c_cb * 8);
        }
#pragma unroll
        for (int i = 0; i < 2; i++) {
            int row = c_row + i * 64;
            CP_ASYNC16(sb + row * RSTRIDE_B + c_cb * 16,
                       Bbase + (size_t)row * F_DIM + k0 + c_cb * 8);
        }
        CP_COMMIT();
    };

    load_stage(0, 0);
    load_stage(1, 1);
    load_stage(2, 2);

    const int lrow = lid & 15;
    const int lchunk = (lid >> 4) * 16;

    // B fragment loader for a given kk half-chunk
    auto load_bf = [&](uint32_t sb, int kk, uint32_t bf[4][2]) {
        const uint32_t koff = kk * 32 + lchunk;
#pragma unroll
        for (int p = 0; p < 2; p++) {
            uint32_t addr = sb + (wn * 32 + p * 16 + lrow) * RSTRIDE_B + koff;
            uint32_t m0, m1, m2, m3;
            LDSM_X4(m0, m1, m2, m3, addr);
            bf[2 * p][0] = m0; bf[2 * p][1] = m2;
            bf[2 * p + 1][0] = m1; bf[2 * p + 1][1] = m3;
        }
    };

    for (int k = 0; k < KITERS; k++) {
        CP_WAIT(2);                  // stage k resident
        __syncthreads();             // all warps done with stage (k-1)%4

        const uint32_t sa = sbase + (k % STAGES) * STAGE_BYTES;
        const uint32_t sb = sa + A_STAGE_BYTES;

        // fragments first (start LDSM immediately), then next-stage prefetch
        uint32_t bf0[4][2], bf1[4][2];
        load_bf(sb, 0, bf0);         // B frags for kk=0

        if (k + 3 < KITERS) load_stage((k + 3) % STAGES, k + 3);

#pragma unroll
        for (int kk = 0; kk < 2; kk++) {
            const uint32_t koff = kk * 32 + lchunk;
            uint32_t af[4][4];
#pragma unroll
            for (int mi = 0; mi < 4; mi++) {
                uint32_t addr = sa + (wm * 64 + mi * 16 + lrow) * RSTRIDE_B + koff;
                LDSM_X4(af[mi][0], af[mi][1], af[mi][2], af[mi][3], addr);
            }
            if (kk == 0) load_bf(sb, 1, bf1);   // prefetch kk=1 B frags
            uint32_t (*bf)[2] = (kk == 0) ? bf0 : bf1;
#pragma unroll
            for (int mi = 0; mi < 4; mi++)
#pragma unroll
                for (int ni = 0; ni < 4; ni++)
                    mma_f16(d[mi][ni], af[mi][0], af[mi][1], af[mi][2], af[mi][3],
                            bf[ni][0], bf[ni][1]);
        }
    }

    // ---- epilogue: direct global float2 stores ----
#pragma unroll
    for (int mi = 0; mi < 4; mi++) {
        const int row = n0 + wm * 64 + mi * 16 + g;
        float* r0 = out + ((size_t)b * N_DIM + row) * L_DIM;
        float* r1 = r0 + 8 * L_DIM;
#pragma unroll
        for (int ni = 0; ni < 4; ni++) {
            const int l = l0 + wn * 32 + ni * 8 + 2 * t;
            if (l < L_DIM) {
                *reinterpret_cast<float2*>(r0 + l) =
                    make_float2(d[mi][ni][0], d[mi][ni][1]);
                *reinterpret_cast<float2*>(r1 + l) =
                    make_float2(d[mi][ni][2], d[mi][ni][3]);
            }
        }
    }
}

// ============================================================================
// host
// ============================================================================
extern "C" void kernel_launch(void* const* d_in, const int* in_sizes, int n_in,
                              void* d_out, int out_size) {
    const float* X = (const float*)d_in[0];
    const float* C = (const float*)d_in[1];
    const float* W = (const float*)d_in[2];
    for (int i = 0; i < n_in; i++) {
        if (in_sizes[i] == B_DIM * F_DIM * L_DIM) X = (const float*)d_in[i];
        else if (in_sizes[i] == F_DIM * N_DIM)    C = (const float*)d_in[i];
        else if (in_sizes[i] == N_DIM)            W = (const float*)d_in[i];
    }

    cudaFuncSetAttribute(gemm_kernel,
                         cudaFuncAttributeMaxDynamicSharedMemorySize, SMEM_BYTES);

    // merged prep: grid xy covers X tiles (32 x 16); z: 32 X-slices + 2 A-slices
    prep_kernel<<<dim3(LPAD / 32, F_DIM / 64, PZ_A), dim3(32, 8)>>>(X, C, W);
    gemm_kernel<<<dim3(N_DIM / TM, LPAD / TN, B_DIM), 256, SMEM_BYTES>>>(
        (float*)d_out);
}